// round 1
// baseline (speedup 1.0000x reference)
#include <cuda_runtime.h>
#include <math.h>

// Problem constants
#define B_SZ 2
#define L_SZ 2048
#define D_SZ 1024
#define N_SZ 16
#define M_TOT (B_SZ * L_SZ)      // 4096 rows of u
#define K_DIM D_SZ               // 1024
#define NOUT_BC (D_SZ * N_SZ)    // 16384

// Scratch (device globals: allocation-free rule)
__device__ float g_dt[M_TOT * D_SZ];                       // 16 MB
__device__ float g_Bt[(size_t)M_TOT * NOUT_BC];            // 256 MB
__device__ float g_Ct[(size_t)M_TOT * NOUT_BC];            // 256 MB

// ---------------------------------------------------------------------------
// packed f32x2 helpers (sm_100+ FFMA2 — only reachable via PTX)
// ---------------------------------------------------------------------------
__device__ __forceinline__ void fma2(unsigned long long& d,
                                     unsigned long long a,
                                     unsigned long long b) {
    asm("fma.rn.f32x2 %0, %1, %2, %0;" : "+l"(d) : "l"(a), "l"(b));
}
__device__ __forceinline__ unsigned long long pack2(float lo, float hi) {
    unsigned long long r;
    asm("mov.b64 %0, {%1, %2};" : "=l"(r) : "f"(lo), "f"(hi));
    return r;
}

__device__ __forceinline__ float softplus_f(float x) {
    return (x > 20.0f) ? x : log1pf(expf(x));
}

// ---------------------------------------------------------------------------
// GEMM: out[m, o] = dot(U[m, :], W[o, :]) + epilogue
//   U: (M_TOT, K_DIM) row-major, W: (Nout, K_DIM) row-major  (NT gemm)
//   mode 0: out = softplus(val + bias[o] + bias2[o])   (dt path)
//   mode 1: out = val + bias[o]                        (B/C path)
// Tiles: BM=BN=128, BK=16; 256 threads; per-thread 8x8 via f32x2 (4 m-pairs x 8 n)
// ---------------------------------------------------------------------------
#define BM 128
#define BN 128
#define BK 16

__global__ __launch_bounds__(256)
void gemm_nt_kernel(const float* __restrict__ U, const float* __restrict__ W,
                    const float* __restrict__ bias, const float* __restrict__ bias2,
                    float* __restrict__ out, int Nout, int mode)
{
    __shared__ __align__(16) float As[BK][BM + 4];
    __shared__ __align__(16) float Ws[BK][BN + 4];

    const int tid = threadIdx.x;
    const int bx = blockIdx.x;   // Nout tile
    const int by = blockIdx.y;   // M tile

    const float* Ablk = U + (size_t)by * BM * K_DIM;
    const float* Wblk = W + (size_t)bx * BN * K_DIM;

    const int tx = tid & 15;     // 16 cols of threads -> 128 n
    const int ty = tid >> 4;     // 16 rows of threads -> 128 m

    unsigned long long acc[4][8];
#pragma unroll
    for (int i = 0; i < 4; ++i)
#pragma unroll
        for (int j = 0; j < 8; ++j) acc[i][j] = 0ull;

    for (int k0 = 0; k0 < K_DIM; k0 += BK) {
        // load 128x16 tiles of U and W (each thread: 2 float4 from each)
#pragma unroll
        for (int r = 0; r < 2; ++r) {
            int id = tid + r * 256;          // 0..511 float4 slots
            int row = id >> 2;
            int c4 = (id & 3) << 2;
            float4 va = *(const float4*)&Ablk[(size_t)row * K_DIM + k0 + c4];
            As[c4 + 0][row] = va.x; As[c4 + 1][row] = va.y;
            As[c4 + 2][row] = va.z; As[c4 + 3][row] = va.w;
            float4 vw = *(const float4*)&Wblk[(size_t)row * K_DIM + k0 + c4];
            Ws[c4 + 0][row] = vw.x; Ws[c4 + 1][row] = vw.y;
            Ws[c4 + 2][row] = vw.z; Ws[c4 + 3][row] = vw.w;
        }
        __syncthreads();

#pragma unroll
        for (int k = 0; k < BK; ++k) {
            unsigned long long mp[4];
#pragma unroll
            for (int i = 0; i < 4; ++i)
                mp[i] = *reinterpret_cast<const unsigned long long*>(&As[k][ty * 8 + 2 * i]);
            float4 n0 = *(const float4*)&Ws[k][tx * 8];
            float4 n1 = *(const float4*)&Ws[k][tx * 8 + 4];
            unsigned long long bd[8];
            bd[0] = pack2(n0.x, n0.x); bd[1] = pack2(n0.y, n0.y);
            bd[2] = pack2(n0.z, n0.z); bd[3] = pack2(n0.w, n0.w);
            bd[4] = pack2(n1.x, n1.x); bd[5] = pack2(n1.y, n1.y);
            bd[6] = pack2(n1.z, n1.z); bd[7] = pack2(n1.w, n1.w);
#pragma unroll
            for (int i = 0; i < 4; ++i)
#pragma unroll
                for (int j = 0; j < 8; ++j) fma2(acc[i][j], mp[i], bd[j]);
        }
        __syncthreads();
    }

    // epilogue
    const int colBase = bx * BN + tx * 8;
#pragma unroll
    for (int i = 0; i < 4; ++i) {
        const int r = by * BM + ty * 8 + 2 * i;
        float lo[8], hi[8];
#pragma unroll
        for (int j = 0; j < 8; ++j) {
            lo[j] = __uint_as_float((unsigned)(acc[i][j] & 0xffffffffull));
            hi[j] = __uint_as_float((unsigned)(acc[i][j] >> 32));
        }
#pragma unroll
        for (int j = 0; j < 8; ++j) {
            float c = bias[colBase + j];
            if (mode == 0) {
                float c2 = bias2[colBase + j];
                lo[j] = softplus_f(lo[j] + c + c2);
                hi[j] = softplus_f(hi[j] + c + c2);
            } else {
                lo[j] += c;
                hi[j] += c;
            }
        }
        *(float4*)&out[(size_t)r * Nout + colBase]     = make_float4(lo[0], lo[1], lo[2], lo[3]);
        *(float4*)&out[(size_t)r * Nout + colBase + 4] = make_float4(lo[4], lo[5], lo[6], lo[7]);
        *(float4*)&out[(size_t)(r + 1) * Nout + colBase]     = make_float4(hi[0], hi[1], hi[2], hi[3]);
        *(float4*)&out[(size_t)(r + 1) * Nout + colBase + 4] = make_float4(hi[4], hi[5], hi[6], hi[7]);
    }
}

// ---------------------------------------------------------------------------
// Scan: 16 lanes per (b,d) pair (one per state n), 2 pairs per warp with
// adjacent d so the warp's Bt/Ct loads are one 128B line.
// h_{t} = exp(dt*A)*h_{t-1} + ((exp(dt*A)-1)/A)*Bt*u ;  y = sum_n Ct*h + Dskip*u
// ---------------------------------------------------------------------------
__global__ __launch_bounds__(256)
void scan_kernel(const float* __restrict__ u, const float* __restrict__ log_A,
                 const float* __restrict__ D_skip,
                 const float* __restrict__ dt, const float* __restrict__ Bt,
                 const float* __restrict__ Ct, float* __restrict__ out)
{
    const int tid = threadIdx.x;
    const int lane = tid & 31;
    const int half = lane >> 4;          // which pair in the warp
    const int n = lane & 15;             // state index
    const int warp = tid >> 5;
    const int p = blockIdx.x * 16 + warp * 2 + half;   // (b,d) pair index
    const int b = p >> 10;               // / D_SZ
    const int d = p & 1023;              // % D_SZ

    const float A = -expf(log_A[d * N_SZ + n]);
    const float invA = 1.0f / A;
    const float Dsk = D_skip[d];

    size_t base = (size_t)b * L_SZ * D_SZ + d;      // index at t=0 into (m,d)
    size_t baseN = base * N_SZ + n;                 // index at t=0 into (m,d,n)

    const float* dtp = dt + base;
    const float* up  = u + base;
    float* op        = out + base;
    const float* bp  = Bt + baseN;
    const float* cp  = Ct + baseN;

    float h = 0.0f;
#pragma unroll 4
    for (int t = 0; t < L_SZ; ++t) {
        float dtv = *dtp;
        float uv  = *up;
        float btv = *bp;
        float ctv = *cp;

        float a = __expf(dtv * A);
        float x = (a - 1.0f) * invA * btv * uv;
        h = fmaf(a, h, x);

        float prod = ctv * h;
        prod += __shfl_xor_sync(0xffffffffu, prod, 1);
        prod += __shfl_xor_sync(0xffffffffu, prod, 2);
        prod += __shfl_xor_sync(0xffffffffu, prod, 4);
        prod += __shfl_xor_sync(0xffffffffu, prod, 8);
        if (n == 0) *op = fmaf(Dsk, uv, prod);

        dtp += D_SZ; up += D_SZ; op += D_SZ;
        bp += (size_t)D_SZ * N_SZ;
        cp += (size_t)D_SZ * N_SZ;
    }
}

// ---------------------------------------------------------------------------
// Launch: inputs in metadata order:
// u, log_A, D_skip, dt_bias, W_dt, b_dt, W_B, b_B, W_C, b_C
// ---------------------------------------------------------------------------
extern "C" void kernel_launch(void* const* d_in, const int* in_sizes, int n_in,
                              void* d_out, int out_size)
{
    const float* u       = (const float*)d_in[0];
    const float* log_A   = (const float*)d_in[1];
    const float* D_skip  = (const float*)d_in[2];
    const float* dt_bias = (const float*)d_in[3];
    const float* W_dt    = (const float*)d_in[4];
    const float* b_dt    = (const float*)d_in[5];
    const float* W_B     = (const float*)d_in[6];
    const float* b_B     = (const float*)d_in[7];
    const float* W_C     = (const float*)d_in[8];
    const float* b_C     = (const float*)d_in[9];
    float* out = (float*)d_out;

    float* dt_buf; cudaGetSymbolAddress((void**)&dt_buf, g_dt);
    float* B_buf;  cudaGetSymbolAddress((void**)&B_buf, g_Bt);
    float* C_buf;  cudaGetSymbolAddress((void**)&C_buf, g_Ct);

    dim3 block(256);
    // dt = softplus(u @ W_dt^T + b_dt + dt_bias)
    dim3 grid_dt(D_SZ / BN, M_TOT / BM);           // (8, 32)
    gemm_nt_kernel<<<grid_dt, block>>>(u, W_dt, b_dt, dt_bias, dt_buf, D_SZ, 0);
    // Bt = u @ W_B^T + b_B   (row-major (m, d*N+n) == (b,l,d,n))
    dim3 grid_bc(NOUT_BC / BN, M_TOT / BM);        // (128, 32)
    gemm_nt_kernel<<<grid_bc, block>>>(u, W_B, b_B, nullptr, B_buf, NOUT_BC, 1);
    gemm_nt_kernel<<<grid_bc, block>>>(u, W_C, b_C, nullptr, C_buf, NOUT_BC, 1);

    // scan: 2048 (b,d) pairs, 16 pairs per 256-thread block
    scan_kernel<<<(B_SZ * D_SZ) / 16, block>>>(u, log_A, D_skip, dt_buf, B_buf, C_buf, out);
}

// round 3
// speedup vs baseline: 3.4282x; 3.4282x over previous
#include <cuda_runtime.h>
#include <cstdint>
#include <math.h>

// Problem constants
#define B_SZ 2
#define L_SZ 2048
#define D_SZ 1024
#define N_SZ 16
#define M_TOT (B_SZ * L_SZ)      // 4096
#define K_DIM D_SZ               // 1024
#define NOUT_BC (D_SZ * N_SZ)    // 16384

#define NC 8                     // scan chunks
#define CL (L_SZ / NC)           // 256

// Scratch (device globals: allocation-free rule)
__device__ float g_dt[M_TOT * D_SZ];                       // 16 MB
__device__ float g_Bt[(size_t)M_TOT * NOUT_BC];            // 256 MB
__device__ float g_Ct[(size_t)M_TOT * NOUT_BC];            // 256 MB
// tf32-rounded copies of U and weights (pre-pass, so the GEMM does no cvt)
__device__ float g_Uc[M_TOT * K_DIM];                      // 16 MB
__device__ float g_Wdtc[D_SZ * K_DIM];                     // 4 MB
__device__ float g_WBc[(size_t)NOUT_BC * K_DIM];           // 64 MB
__device__ float g_WCc[(size_t)NOUT_BC * K_DIM];           // 64 MB
// scan chunk state
__device__ float g_P[B_SZ * D_SZ * NC * N_SZ];             // 1 MB
__device__ float g_H[B_SZ * D_SZ * NC * N_SZ];             // 1 MB
__device__ float g_hs[B_SZ * D_SZ * NC * N_SZ];            // 1 MB

// ---------------------------------------------------------------------------
// helpers
// ---------------------------------------------------------------------------
__device__ __forceinline__ uint32_t smem_u32(const void* p) {
    uint32_t a;
    asm("{ .reg .u64 t; cvta.to.shared.u64 t, %1; cvt.u32.u64 %0, t; }"
        : "=r"(a) : "l"(p));
    return a;
}
__device__ __forceinline__ void cp_async16(uint32_t dst, const void* src) {
    asm volatile("cp.async.cg.shared.global [%0], [%1], 16;"
                 :: "r"(dst), "l"(src) : "memory");
}
__device__ __forceinline__ float tf32_rna(float x) {
    float r;
    asm("cvt.rna.tf32.f32 %0, %1;" : "=f"(r) : "f"(x));
    return r;
}
__device__ __forceinline__ float softplus_f(float x) {
    return (x > 20.0f) ? x : log1pf(expf(x));
}
__device__ __forceinline__ void mma_tf32(float* c, const uint32_t* a,
                                         const uint32_t* b) {
    asm volatile(
        "mma.sync.aligned.m16n8k8.row.col.f32.tf32.tf32.f32 "
        "{%0,%1,%2,%3}, {%4,%5,%6,%7}, {%8,%9}, {%0,%1,%2,%3};"
        : "+f"(c[0]), "+f"(c[1]), "+f"(c[2]), "+f"(c[3])
        : "r"(a[0]), "r"(a[1]), "r"(a[2]), "r"(a[3]), "r"(b[0]), "r"(b[1]));
}

// ---------------------------------------------------------------------------
// tf32 rounding pre-pass (memory-bound)
// ---------------------------------------------------------------------------
__global__ __launch_bounds__(256)
void tf32_round_kernel(const float* __restrict__ in, float* __restrict__ out,
                       int n4) {
    int i = blockIdx.x * blockDim.x + threadIdx.x;
    if (i < n4) {
        float4 v = ((const float4*)in)[i];
        v.x = tf32_rna(v.x); v.y = tf32_rna(v.y);
        v.z = tf32_rna(v.z); v.w = tf32_rna(v.w);
        ((float4*)out)[i] = v;
    }
}

// ---------------------------------------------------------------------------
// GEMM (mma.sync tf32): out[m,o] = dot(U[m,:], W[o,:]) + epilogue
//   mode 0: softplus(val + bias + bias2)   mode 1: val + bias
// 256 threads (8 warps), CTA tile 128x128, BK=32, cp.async double buffer.
// Warp grid 4(m) x 2(n): each warp 32x64 = 2 mtiles x 8 ntiles of m16n8k8.
// ---------------------------------------------------------------------------
#define ASTRIDE 36               // 32 + 4 pad (floats)
#define TILE_F (128 * ASTRIDE)   // floats per tile
#define GEMM_SMEM (2 * 2 * TILE_F * 4)   // 73728 bytes

__global__ __launch_bounds__(256)
void gemm_mma(const float* __restrict__ U, const float* __restrict__ W,
              const float* __restrict__ bias, const float* __restrict__ bias2,
              float* __restrict__ out, int Nout, int mode)
{
    extern __shared__ float sm[];
    const int tid = threadIdx.x;
    const int wid = tid >> 5;
    const int lane = tid & 31;
    const int bx = blockIdx.x;      // N tile
    const int by = blockIdx.y;      // M tile
    const int warp_m = wid & 3, warp_n = wid >> 2;
    const int m0 = warp_m * 32, n0 = warp_n * 64;
    const int g = lane >> 2, t4 = lane & 3;

    const float* Ag = U + (size_t)(by * 128) * K_DIM;
    const float* Bg = W + (size_t)(bx * 128) * K_DIM;

    float acc[2][8][4];
#pragma unroll
    for (int mt = 0; mt < 2; ++mt)
#pragma unroll
        for (int nt = 0; nt < 8; ++nt)
#pragma unroll
            for (int j = 0; j < 4; ++j) acc[mt][nt][j] = 0.0f;

    const int NK = K_DIM / 32;      // 32 k-tiles

    // stage k-tile `it` into buffer `buf`
    auto issue = [&](int it, int buf) {
        float* As = sm + buf * 2 * TILE_F;
        float* Bs = As + TILE_F;
        const int kc = it * 32;
#pragma unroll
        for (int i = 0; i < 4; ++i) {
            int id = tid + i * 256;     // 0..1023
            int row = id >> 3;
            int q = id & 7;
            cp_async16(smem_u32(As + row * ASTRIDE + q * 4),
                       Ag + (size_t)row * K_DIM + kc + q * 4);
            cp_async16(smem_u32(Bs + row * ASTRIDE + q * 4),
                       Bg + (size_t)row * K_DIM + kc + q * 4);
        }
        asm volatile("cp.async.commit_group;" ::: "memory");
    };

    issue(0, 0);
    for (int it = 0; it < NK; ++it) {
        const int buf = it & 1;
        if (it + 1 < NK) {
            issue(it + 1, buf ^ 1);
            asm volatile("cp.async.wait_group 1;" ::: "memory");
        } else {
            asm volatile("cp.async.wait_group 0;" ::: "memory");
        }
        __syncthreads();

        const float* As = sm + buf * 2 * TILE_F;
        const float* Bs = As + TILE_F;
#pragma unroll
        for (int ks = 0; ks < 4; ++ks) {
            const int k = ks * 8;
            uint32_t a[2][4], b[8][2];
#pragma unroll
            for (int mt = 0; mt < 2; ++mt) {
                const int r = m0 + mt * 16 + g;
                a[mt][0] = __float_as_uint(As[r * ASTRIDE + k + t4]);
                a[mt][1] = __float_as_uint(As[(r + 8) * ASTRIDE + k + t4]);
                a[mt][2] = __float_as_uint(As[r * ASTRIDE + k + t4 + 4]);
                a[mt][3] = __float_as_uint(As[(r + 8) * ASTRIDE + k + t4 + 4]);
            }
#pragma unroll
            for (int nt = 0; nt < 8; ++nt) {
                const int c = n0 + nt * 8 + g;
                b[nt][0] = __float_as_uint(Bs[c * ASTRIDE + k + t4]);
                b[nt][1] = __float_as_uint(Bs[c * ASTRIDE + k + t4 + 4]);
            }
#pragma unroll
            for (int mt = 0; mt < 2; ++mt)
#pragma unroll
                for (int nt = 0; nt < 8; ++nt)
                    mma_tf32(acc[mt][nt], a[mt], b[nt]);
        }
        __syncthreads();
    }

    // Epilogue: fragment -> global (float2 stores, bias / softplus fused)
#pragma unroll
    for (int nt = 0; nt < 8; ++nt) {
        const int col = bx * 128 + n0 + nt * 8 + t4 * 2;
        float b0 = bias[col], b1 = bias[col + 1];
        float e0 = 0.f, e1 = 0.f;
        if (mode == 0) { e0 = bias2[col]; e1 = bias2[col + 1]; }
#pragma unroll
        for (int mt = 0; mt < 2; ++mt) {
            const int row = by * 128 + m0 + mt * 16 + g;
            float v0 = acc[mt][nt][0] + b0;
            float v1 = acc[mt][nt][1] + b1;
            float v2 = acc[mt][nt][2] + b0;
            float v3 = acc[mt][nt][3] + b1;
            if (mode == 0) {
                v0 = softplus_f(v0 + e0); v1 = softplus_f(v1 + e1);
                v2 = softplus_f(v2 + e0); v3 = softplus_f(v3 + e1);
            }
            *(float2*)&out[(size_t)row * Nout + col] = make_float2(v0, v1);
            *(float2*)&out[(size_t)(row + 8) * Nout + col] = make_float2(v2, v3);
        }
    }
}

// ---------------------------------------------------------------------------
// Chunked scan.
// Group = (b, d, chunk); 16 lanes per group (one per n); 2 groups per warp
// (adjacent d, same chunk) so Bt/Ct lane loads are one 128B line.
// ---------------------------------------------------------------------------
__global__ __launch_bounds__(256)
void scan_pass1(const float* __restrict__ u, const float* __restrict__ log_A,
                const float* __restrict__ dt, const float* __restrict__ Bt,
                float* __restrict__ P, float* __restrict__ H)
{
    const int tid = threadIdx.x;
    const int lane = tid & 31;
    const int half = lane >> 4;
    const int n = lane & 15;
    const int warp = tid >> 5;
    const int p = blockIdx.x * 16 + warp * 2 + half;   // (b,d) pair
    const int c = blockIdx.y;                          // chunk
    const int b = p >> 10;
    const int d = p & 1023;

    const float A = -expf(log_A[d * N_SZ + n]);
    const float invA = 1.0f / A;

    size_t base = (size_t)b * L_SZ * D_SZ + (size_t)c * CL * D_SZ + d;
    const float* dtp = dt + base;
    const float* up  = u + base;
    const float* bp  = Bt + base * N_SZ + n;

    float h = 0.0f, aprod = 1.0f;
#pragma unroll 4
    for (int t = 0; t < CL; ++t) {
        float a = __expf(*dtp * A);
        float x = (a - 1.0f) * invA * (*bp) * (*up);
        h = fmaf(a, h, x);
        aprod *= a;
        dtp += D_SZ; up += D_SZ; bp += (size_t)D_SZ * N_SZ;
    }
    const int idx = (p * NC + c) * N_SZ + n;
    P[idx] = aprod;
    H[idx] = h;
}

__global__ __launch_bounds__(256)
void scan_chain(const float* __restrict__ P, const float* __restrict__ H,
                float* __restrict__ hs)
{
    const int id = blockIdx.x * blockDim.x + threadIdx.x;  // (p, n)
    const int p = id >> 4;
    const int n = id & 15;
    float h = 0.0f;
#pragma unroll
    for (int c = 0; c < NC; ++c) {
        const int idx = (p * NC + c) * N_SZ + n;
        hs[idx] = h;
        h = fmaf(P[idx], h, H[idx]);
    }
}

__global__ __launch_bounds__(256)
void scan_pass2(const float* __restrict__ u, const float* __restrict__ log_A,
                const float* __restrict__ D_skip,
                const float* __restrict__ dt, const float* __restrict__ Bt,
                const float* __restrict__ Ct, const float* __restrict__ hs,
                float* __restrict__ out)
{
    const int tid = threadIdx.x;
    const int lane = tid & 31;
    const int half = lane >> 4;
    const int n = lane & 15;
    const int warp = tid >> 5;
    const int p = blockIdx.x * 16 + warp * 2 + half;
    const int c = blockIdx.y;
    const int b = p >> 10;
    const int d = p & 1023;

    const float A = -expf(log_A[d * N_SZ + n]);
    const float invA = 1.0f / A;
    const float Dsk = D_skip[d];

    size_t base = (size_t)b * L_SZ * D_SZ + (size_t)c * CL * D_SZ + d;
    const float* dtp = dt + base;
    const float* up  = u + base;
    float* op        = out + base;
    const float* bp  = Bt + base * N_SZ + n;
    const float* cp  = Ct + base * N_SZ + n;

    float h = hs[(p * NC + c) * N_SZ + n];
#pragma unroll 4
    for (int t = 0; t < CL; ++t) {
        float uv = *up;
        float a = __expf(*dtp * A);
        float x = (a - 1.0f) * invA * (*bp) * uv;
        h = fmaf(a, h, x);
        float prod = (*cp) * h;
        prod += __shfl_xor_sync(0xffffffffu, prod, 1);
        prod += __shfl_xor_sync(0xffffffffu, prod, 2);
        prod += __shfl_xor_sync(0xffffffffu, prod, 4);
        prod += __shfl_xor_sync(0xffffffffu, prod, 8);
        if (n == 0) *op = fmaf(Dsk, uv, prod);
        dtp += D_SZ; up += D_SZ; op += D_SZ;
        bp += (size_t)D_SZ * N_SZ; cp += (size_t)D_SZ * N_SZ;
    }
}

// ---------------------------------------------------------------------------
// Launch. Inputs: u, log_A, D_skip, dt_bias, W_dt, b_dt, W_B, b_B, W_C, b_C
// ---------------------------------------------------------------------------
extern "C" void kernel_launch(void* const* d_in, const int* in_sizes, int n_in,
                              void* d_out, int out_size)
{
    const float* u       = (const float*)d_in[0];
    const float* log_A   = (const float*)d_in[1];
    const float* D_skip  = (const float*)d_in[2];
    const float* dt_bias = (const float*)d_in[3];
    const float* W_dt    = (const float*)d_in[4];
    const float* b_dt    = (const float*)d_in[5];
    const float* W_B     = (const float*)d_in[6];
    const float* b_B     = (const float*)d_in[7];
    const float* W_C     = (const float*)d_in[8];
    const float* b_C     = (const float*)d_in[9];
    float* out = (float*)d_out;

    float *dt_buf, *B_buf, *C_buf, *Uc, *Wdtc, *WBc, *WCc, *P, *H, *hs;
    cudaGetSymbolAddress((void**)&dt_buf, g_dt);
    cudaGetSymbolAddress((void**)&B_buf, g_Bt);
    cudaGetSymbolAddress((void**)&C_buf, g_Ct);
    cudaGetSymbolAddress((void**)&Uc, g_Uc);
    cudaGetSymbolAddress((void**)&Wdtc, g_Wdtc);
    cudaGetSymbolAddress((void**)&WBc, g_WBc);
    cudaGetSymbolAddress((void**)&WCc, g_WCc);
    cudaGetSymbolAddress((void**)&P, g_P);
    cudaGetSymbolAddress((void**)&H, g_H);
    cudaGetSymbolAddress((void**)&hs, g_hs);

    cudaFuncSetAttribute(gemm_mma, cudaFuncAttributeMaxDynamicSharedMemorySize,
                         GEMM_SMEM);

    // tf32-rna pre-rounding (memory-bound)
    tf32_round_kernel<<<(M_TOT * K_DIM / 4 + 255) / 256, 256>>>(u, Uc,
                                                                M_TOT * K_DIM / 4);
    tf32_round_kernel<<<(D_SZ * K_DIM / 4 + 255) / 256, 256>>>(W_dt, Wdtc,
                                                               D_SZ * K_DIM / 4);
    tf32_round_kernel<<<(int)((size_t)NOUT_BC * K_DIM / 4 + 255) / 256, 256>>>(
        W_B, WBc, (int)((size_t)NOUT_BC * K_DIM / 4));
    tf32_round_kernel<<<(int)((size_t)NOUT_BC * K_DIM / 4 + 255) / 256, 256>>>(
        W_C, WCc, (int)((size_t)NOUT_BC * K_DIM / 4));

    // dt = softplus(u @ W_dt^T + b_dt + dt_bias)
    gemm_mma<<<dim3(D_SZ / 128, M_TOT / 128), 256, GEMM_SMEM>>>(
        Uc, Wdtc, b_dt, dt_bias, dt_buf, D_SZ, 0);
    // Bt / Ct = u @ W^T + b   (row-major (m, d*N+n) == (b,l,d,n))
    gemm_mma<<<dim3(NOUT_BC / 128, M_TOT / 128), 256, GEMM_SMEM>>>(
        Uc, WBc, b_B, nullptr, B_buf, NOUT_BC, 1);
    gemm_mma<<<dim3(NOUT_BC / 128, M_TOT / 128), 256, GEMM_SMEM>>>(
        Uc, WCc, b_C, nullptr, C_buf, NOUT_BC, 1);

    // chunked scan
    dim3 sgrid(B_SZ * D_SZ / 16, NC);
    scan_pass1<<<sgrid, 256>>>(u, log_A, dt_buf, B_buf, P, H);
    scan_chain<<<B_SZ * D_SZ * N_SZ / 256, 256>>>(P, H, hs);
    scan_pass2<<<sgrid, 256>>>(u, log_A, D_skip, dt_buf, B_buf, C_buf, hs, out);
}

// round 4
// speedup vs baseline: 3.7768x; 1.1017x over previous
#include <cuda_runtime.h>
#include <cstdint>
#include <math.h>

// Problem constants
#define B_SZ 2
#define L_SZ 2048
#define D_SZ 1024
#define N_SZ 16
#define M_TOT (B_SZ * L_SZ)      // 4096
#define K_DIM D_SZ               // 1024
#define NOUT_BC (D_SZ * N_SZ)    // 16384

#define NC 8                     // scan chunks
#define CL (L_SZ / NC)           // 256

// Scratch (device globals: allocation-free rule)
__device__ float g_dt[M_TOT * D_SZ];                       // 16 MB
__device__ float g_Bt[(size_t)M_TOT * NOUT_BC];            // 256 MB
__device__ float g_Ct[(size_t)M_TOT * NOUT_BC];            // 256 MB
// tf32-rounded copies of U and weights
__device__ float g_Uc[M_TOT * K_DIM];                      // 16 MB
__device__ float g_Wdtc[D_SZ * K_DIM];                     // 4 MB
__device__ float g_WBc[(size_t)NOUT_BC * K_DIM];           // 64 MB
__device__ float g_WCc[(size_t)NOUT_BC * K_DIM];           // 64 MB
// scan chunk state
__device__ float g_P[B_SZ * D_SZ * NC * N_SZ];
__device__ float g_H[B_SZ * D_SZ * NC * N_SZ];
__device__ float g_hs[B_SZ * D_SZ * NC * N_SZ];

// ---------------------------------------------------------------------------
// helpers
// ---------------------------------------------------------------------------
__device__ __forceinline__ uint32_t smem_u32(const void* p) {
    uint32_t a;
    asm("{ .reg .u64 t; cvta.to.shared.u64 t, %1; cvt.u32.u64 %0, t; }"
        : "=r"(a) : "l"(p));
    return a;
}
__device__ __forceinline__ void cp_async16(uint32_t dst, const void* src) {
    asm volatile("cp.async.cg.shared.global [%0], [%1], 16;"
                 :: "r"(dst), "l"(src) : "memory");
}
__device__ __forceinline__ float tf32_rna(float x) {
    float r;
    asm("cvt.rna.tf32.f32 %0, %1;" : "=f"(r) : "f"(x));
    return r;
}
__device__ __forceinline__ float softplus_f(float x) {
    return (x > 20.0f) ? x : log1pf(expf(x));
}
__device__ __forceinline__ void mma_tf32(float* c, const uint32_t* a,
                                         const uint32_t* b) {
    asm volatile(
        "mma.sync.aligned.m16n8k8.row.col.f32.tf32.tf32.f32 "
        "{%0,%1,%2,%3}, {%4,%5,%6,%7}, {%8,%9}, {%0,%1,%2,%3};"
        : "+f"(c[0]), "+f"(c[1]), "+f"(c[2]), "+f"(c[3])
        : "r"(a[0]), "r"(a[1]), "r"(a[2]), "r"(a[3]), "r"(b[0]), "r"(b[1]));
}
__device__ __forceinline__ void ldsm_x4(uint32_t* r, uint32_t addr) {
    asm volatile("ldmatrix.sync.aligned.m8n8.x4.shared.b16 {%0,%1,%2,%3}, [%4];"
                 : "=r"(r[0]), "=r"(r[1]), "=r"(r[2]), "=r"(r[3]) : "r"(addr));
}

// ---------------------------------------------------------------------------
// tf32 rounding pre-pass (memory-bound)
// ---------------------------------------------------------------------------
__global__ __launch_bounds__(256)
void tf32_round_kernel(const float* __restrict__ in, float* __restrict__ out,
                       int n4) {
    int i = blockIdx.x * blockDim.x + threadIdx.x;
    if (i < n4) {
        float4 v = ((const float4*)in)[i];
        v.x = tf32_rna(v.x); v.y = tf32_rna(v.y);
        v.z = tf32_rna(v.z); v.w = tf32_rna(v.w);
        ((float4*)out)[i] = v;
    }
}

// ---------------------------------------------------------------------------
// GEMM (mma.sync tf32 + ldmatrix): out[m,o] = dot(U[m,:], W[o,:]) + epilogue
//   mode 0: softplus(val + bias + bias2)   mode 1: val + bias
// 256 threads (8 warps), CTA tile 128x128, BK=32, cp.async double buffer.
// Warp grid 4(m) x 2(n): each warp 32x64 = 2 mtiles x 8 ntiles of m16n8k8.
// Fragments via ldmatrix.m8n8.x4.b16 (8x4 b32 == 8x8 b16 submatrices).
// ---------------------------------------------------------------------------
#define ASTRIDE 36               // 32 + 4 pad (floats); 144B rows, LDSM-conflict-free
#define TILE_F (128 * ASTRIDE)   // floats per tile
#define GEMM_SMEM (2 * 2 * TILE_F * 4)   // 73728 bytes

__global__ __launch_bounds__(256, 2)
void gemm_mma(const float* __restrict__ U, const float* __restrict__ W,
              const float* __restrict__ bias, const float* __restrict__ bias2,
              float* __restrict__ out, int Nout, int mode)
{
    extern __shared__ float sm[];
    const int tid = threadIdx.x;
    const int wid = tid >> 5;
    const int lane = tid & 31;
    const int bx = blockIdx.x;      // N tile
    const int by = blockIdx.y;      // M tile
    const int warp_m = wid & 3, warp_n = wid >> 2;
    const int m0 = warp_m * 32, n0 = warp_n * 64;
    const int g = lane >> 2, t4 = lane & 3;

    const float* Ag = U + (size_t)(by * 128) * K_DIM;
    const float* Bg = W + (size_t)(bx * 128) * K_DIM;

    // per-lane ldmatrix byte offsets (within a tile)
    const int sel = lane >> 3;      // which 8x8(b16) submatrix this lane addresses
    const int lr  = lane & 7;       // row within submatrix
    // A x4 matrices: {(+0,k), (+8,k), (+0,k+4), (+8,k+4)}
    uint32_t aoff[2];
#pragma unroll
    for (int mt = 0; mt < 2; ++mt) {
        int row = m0 + mt * 16 + lr + (sel & 1) * 8;
        int kad = (sel >> 1) * 4;
        aoff[mt] = (uint32_t)((row * ASTRIDE + kad) * 4);
    }
    // B x4 matrices (nt pair): {(nt,k), (nt,k+4), (nt+1,k), (nt+1,k+4)}
    uint32_t boff[4];
#pragma unroll
    for (int ntp = 0; ntp < 4; ++ntp) {
        int row = n0 + (2 * ntp + (sel >> 1)) * 8 + lr;
        int kad = (sel & 1) * 4;
        boff[ntp] = (uint32_t)((row * ASTRIDE + kad) * 4);
    }

    float acc[2][8][4];
#pragma unroll
    for (int mt = 0; mt < 2; ++mt)
#pragma unroll
        for (int nt = 0; nt < 8; ++nt)
#pragma unroll
            for (int j = 0; j < 4; ++j) acc[mt][nt][j] = 0.0f;

    const int NK = K_DIM / 32;      // 32 k-tiles
    const uint32_t sm_u = smem_u32(sm);

    auto issue = [&](int it, int buf) {
        float* As = sm + buf * 2 * TILE_F;
        float* Bs = As + TILE_F;
        const int kc = it * 32;
#pragma unroll
        for (int i = 0; i < 4; ++i) {
            int id = tid + i * 256;     // 0..1023
            int row = id >> 3;
            int q = id & 7;
            cp_async16(smem_u32(As + row * ASTRIDE + q * 4),
                       Ag + (size_t)row * K_DIM + kc + q * 4);
            cp_async16(smem_u32(Bs + row * ASTRIDE + q * 4),
                       Bg + (size_t)row * K_DIM + kc + q * 4);
        }
        asm volatile("cp.async.commit_group;" ::: "memory");
    };

    issue(0, 0);
    for (int it = 0; it < NK; ++it) {
        const int buf = it & 1;
        if (it + 1 < NK) {
            issue(it + 1, buf ^ 1);
            asm volatile("cp.async.wait_group 1;" ::: "memory");
        } else {
            asm volatile("cp.async.wait_group 0;" ::: "memory");
        }
        __syncthreads();

        const uint32_t As_u = sm_u + (uint32_t)(buf * 2 * TILE_F * 4);
        const uint32_t Bs_u = As_u + (uint32_t)(TILE_F * 4);
#pragma unroll
        for (int ks = 0; ks < 4; ++ks) {
            const uint32_t kb = ks * 32;          // 8 floats per ks step
            uint32_t a[2][4], b[4][4];
            ldsm_x4(a[0], As_u + aoff[0] + kb);
            ldsm_x4(a[1], As_u + aoff[1] + kb);
#pragma unroll
            for (int ntp = 0; ntp < 4; ++ntp)
                ldsm_x4(b[ntp], Bs_u + boff[ntp] + kb);
#pragma unroll
            for (int mt = 0; mt < 2; ++mt)
#pragma unroll
                for (int nt = 0; nt < 8; ++nt)
                    mma_tf32(acc[mt][nt], a[mt], &b[nt >> 1][(nt & 1) * 2]);
        }
        __syncthreads();
    }

    // Epilogue: fragment -> global (float2 stores, bias / softplus fused)
#pragma unroll
    for (int nt = 0; nt < 8; ++nt) {
        const int col = bx * 128 + n0 + nt * 8 + t4 * 2;
        float b0 = bias[col], b1 = bias[col + 1];
        float e0 = 0.f, e1 = 0.f;
        if (mode == 0) { e0 = bias2[col]; e1 = bias2[col + 1]; }
#pragma unroll
        for (int mt = 0; mt < 2; ++mt) {
            const int row = by * 128 + m0 + mt * 16 + g;
            float v0 = acc[mt][nt][0] + b0;
            float v1 = acc[mt][nt][1] + b1;
            float v2 = acc[mt][nt][2] + b0;
            float v3 = acc[mt][nt][3] + b1;
            if (mode == 0) {
                v0 = softplus_f(v0 + e0); v1 = softplus_f(v1 + e1);
                v2 = softplus_f(v2 + e0); v3 = softplus_f(v3 + e1);
            }
            *(float2*)&out[(size_t)row * Nout + col] = make_float2(v0, v1);
            *(float2*)&out[(size_t)(row + 8) * Nout + col] = make_float2(v2, v3);
        }
    }
}

// ---------------------------------------------------------------------------
// Chunked scan (unchanged from passing R3 kernel)
// ---------------------------------------------------------------------------
__global__ __launch_bounds__(256)
void scan_pass1(const float* __restrict__ u, const float* __restrict__ log_A,
                const float* __restrict__ dt, const float* __restrict__ Bt,
                float* __restrict__ P, float* __restrict__ H)
{
    const int tid = threadIdx.x;
    const int lane = tid & 31;
    const int half = lane >> 4;
    const int n = lane & 15;
    const int warp = tid >> 5;
    const int p = blockIdx.x * 16 + warp * 2 + half;
    const int c = blockIdx.y;
    const int b = p >> 10;
    const int d = p & 1023;

    const float A = -expf(log_A[d * N_SZ + n]);
    const float invA = 1.0f / A;

    size_t base = (size_t)b * L_SZ * D_SZ + (size_t)c * CL * D_SZ + d;
    const float* dtp = dt + base;
    const float* up  = u + base;
    const float* bp  = Bt + base * N_SZ + n;

    float h = 0.0f, aprod = 1.0f;
#pragma unroll 4
    for (int t = 0; t < CL; ++t) {
        float a = __expf(*dtp * A);
        float x = (a - 1.0f) * invA * (*bp) * (*up);
        h = fmaf(a, h, x);
        aprod *= a;
        dtp += D_SZ; up += D_SZ; bp += (size_t)D_SZ * N_SZ;
    }
    const int idx = (p * NC + c) * N_SZ + n;
    P[idx] = aprod;
    H[idx] = h;
}

__global__ __launch_bounds__(256)
void scan_chain(const float* __restrict__ P, const float* __restrict__ H,
                float* __restrict__ hs)
{
    const int id = blockIdx.x * blockDim.x + threadIdx.x;
    const int p = id >> 4;
    const int n = id & 15;
    float h = 0.0f;
#pragma unroll
    for (int c = 0; c < NC; ++c) {
        const int idx = (p * NC + c) * N_SZ + n;
        hs[idx] = h;
        h = fmaf(P[idx], h, H[idx]);
    }
}

__global__ __launch_bounds__(256)
void scan_pass2(const float* __restrict__ u, const float* __restrict__ log_A,
                const float* __restrict__ D_skip,
                const float* __restrict__ dt, const float* __restrict__ Bt,
                const float* __restrict__ Ct, const float* __restrict__ hs,
                float* __restrict__ out)
{
    const int tid = threadIdx.x;
    const int lane = tid & 31;
    const int half = lane >> 4;
    const int n = lane & 15;
    const int warp = tid >> 5;
    const int p = blockIdx.x * 16 + warp * 2 + half;
    const int c = blockIdx.y;
    const int b = p >> 10;
    const int d = p & 1023;

    const float A = -expf(log_A[d * N_SZ + n]);
    const float invA = 1.0f / A;
    const float Dsk = D_skip[d];

    size_t base = (size_t)b * L_SZ * D_SZ + (size_t)c * CL * D_SZ + d;
    const float* dtp = dt + base;
    const float* up  = u + base;
    float* op        = out + base;
    const float* bp  = Bt + base * N_SZ + n;
    const float* cp  = Ct + base * N_SZ + n;

    float h = hs[(p * NC + c) * N_SZ + n];
#pragma unroll 4
    for (int t = 0; t < CL; ++t) {
        float uv = *up;
        float a = __expf(*dtp * A);
        float x = (a - 1.0f) * invA * (*bp) * uv;
        h = fmaf(a, h, x);
        float prod = (*cp) * h;
        prod += __shfl_xor_sync(0xffffffffu, prod, 1);
        prod += __shfl_xor_sync(0xffffffffu, prod, 2);
        prod += __shfl_xor_sync(0xffffffffu, prod, 4);
        prod += __shfl_xor_sync(0xffffffffu, prod, 8);
        if (n == 0) *op = fmaf(Dsk, uv, prod);
        dtp += D_SZ; up += D_SZ; op += D_SZ;
        bp += (size_t)D_SZ * N_SZ; cp += (size_t)D_SZ * N_SZ;
    }
}

// ---------------------------------------------------------------------------
// Launch. Inputs: u, log_A, D_skip, dt_bias, W_dt, b_dt, W_B, b_B, W_C, b_C
// ---------------------------------------------------------------------------
extern "C" void kernel_launch(void* const* d_in, const int* in_sizes, int n_in,
                              void* d_out, int out_size)
{
    const float* u       = (const float*)d_in[0];
    const float* log_A   = (const float*)d_in[1];
    const float* D_skip  = (const float*)d_in[2];
    const float* dt_bias = (const float*)d_in[3];
    const float* W_dt    = (const float*)d_in[4];
    const float* b_dt    = (const float*)d_in[5];
    const float* W_B     = (const float*)d_in[6];
    const float* b_B     = (const float*)d_in[7];
    const float* W_C     = (const float*)d_in[8];
    const float* b_C     = (const float*)d_in[9];
    float* out = (float*)d_out;

    float *dt_buf, *B_buf, *C_buf, *Uc, *Wdtc, *WBc, *WCc, *P, *H, *hs;
    cudaGetSymbolAddress((void**)&dt_buf, g_dt);
    cudaGetSymbolAddress((void**)&B_buf, g_Bt);
    cudaGetSymbolAddress((void**)&C_buf, g_Ct);
    cudaGetSymbolAddress((void**)&Uc, g_Uc);
    cudaGetSymbolAddress((void**)&Wdtc, g_Wdtc);
    cudaGetSymbolAddress((void**)&WBc, g_WBc);
    cudaGetSymbolAddress((void**)&WCc, g_WCc);
    cudaGetSymbolAddress((void**)&P, g_P);
    cudaGetSymbolAddress((void**)&H, g_H);
    cudaGetSymbolAddress((void**)&hs, g_hs);

    cudaFuncSetAttribute(gemm_mma, cudaFuncAttributeMaxDynamicSharedMemorySize,
                         GEMM_SMEM);

    // tf32-rna pre-rounding (memory-bound)
    tf32_round_kernel<<<(M_TOT * K_DIM / 4 + 255) / 256, 256>>>(u, Uc,
                                                                M_TOT * K_DIM / 4);
    tf32_round_kernel<<<(D_SZ * K_DIM / 4 + 255) / 256, 256>>>(W_dt, Wdtc,
                                                               D_SZ * K_DIM / 4);
    tf32_round_kernel<<<(int)((size_t)NOUT_BC * K_DIM / 4 + 255) / 256, 256>>>(
        W_B, WBc, (int)((size_t)NOUT_BC * K_DIM / 4));
    tf32_round_kernel<<<(int)((size_t)NOUT_BC * K_DIM / 4 + 255) / 256, 256>>>(
        W_C, WCc, (int)((size_t)NOUT_BC * K_DIM / 4));

    // dt = softplus(u @ W_dt^T + b_dt + dt_bias)
    gemm_mma<<<dim3(D_SZ / 128, M_TOT / 128), 256, GEMM_SMEM>>>(
        Uc, Wdtc, b_dt, dt_bias, dt_buf, D_SZ, 0);
    // Bt / Ct = u @ W^T + b
    gemm_mma<<<dim3(NOUT_BC / 128, M_TOT / 128), 256, GEMM_SMEM>>>(
        Uc, WBc, b_B, nullptr, B_buf, NOUT_BC, 1);
    gemm_mma<<<dim3(NOUT_BC / 128, M_TOT / 128), 256, GEMM_SMEM>>>(
        Uc, WCc, b_C, nullptr, C_buf, NOUT_BC, 1);

    // chunked scan
    dim3 sgrid(B_SZ * D_SZ / 16, NC);
    scan_pass1<<<sgrid, 256>>>(u, log_A, dt_buf, B_buf, P, H);
    scan_chain<<<B_SZ * D_SZ * N_SZ / 256, 256>>>(P, H, hs);
    scan_pass2<<<sgrid, 256>>>(u, log_A, D_skip, dt_buf, B_buf, C_buf, hs, out);
}

// round 5
// speedup vs baseline: 6.4051x; 1.6959x over previous
#include <cuda_runtime.h>
#include <cuda_fp16.h>
#include <cstdint>
#include <math.h>

// Problem constants
#define B_SZ 2
#define L_SZ 2048
#define D_SZ 1024
#define N_SZ 16
#define M_TOT (B_SZ * L_SZ)      // 4096
#define K_DIM D_SZ               // 1024
#define NOUT_BC (D_SZ * N_SZ)    // 16384

#define NC 8                     // scan chunks
#define CL (L_SZ / NC)           // 256

// Scratch (device globals: allocation-free rule)
__device__ float  g_dt[M_TOT * D_SZ];                       // 16 MB
__device__ __half g_Bt[(size_t)M_TOT * NOUT_BC];            // 128 MB
__device__ __half g_Ct[(size_t)M_TOT * NOUT_BC];            // 128 MB
// fp16 copies of U and weights
__device__ __half g_Uh[M_TOT * K_DIM];                      // 8 MB
__device__ __half g_Wdth[D_SZ * K_DIM];                     // 2 MB
__device__ __half g_WBh[(size_t)NOUT_BC * K_DIM];           // 32 MB
__device__ __half g_WCh[(size_t)NOUT_BC * K_DIM];           // 32 MB
// scan chunk state
__device__ float g_P[B_SZ * D_SZ * NC * N_SZ];
__device__ float g_H[B_SZ * D_SZ * NC * N_SZ];
__device__ float g_hs[B_SZ * D_SZ * NC * N_SZ];

// ---------------------------------------------------------------------------
// helpers
// ---------------------------------------------------------------------------
__device__ __forceinline__ uint32_t smem_u32(const void* p) {
    uint32_t a;
    asm("{ .reg .u64 t; cvta.to.shared.u64 t, %1; cvt.u32.u64 %0, t; }"
        : "=r"(a) : "l"(p));
    return a;
}
__device__ __forceinline__ void cp_async16(uint32_t dst, const void* src) {
    asm volatile("cp.async.cg.shared.global [%0], [%1], 16;"
                 :: "r"(dst), "l"(src) : "memory");
}
__device__ __forceinline__ float softplus_f(float x) {
    return (x > 20.0f) ? x : log1pf(expf(x));
}
// fp16 mma with fp32 accumulate, m16n8k16
__device__ __forceinline__ void mma_f16(float* c, const uint32_t* a,
                                        const uint32_t* b) {
    asm volatile(
        "mma.sync.aligned.m16n8k16.row.col.f32.f16.f16.f32 "
        "{%0,%1,%2,%3}, {%4,%5,%6,%7}, {%8,%9}, {%0,%1,%2,%3};"
        : "+f"(c[0]), "+f"(c[1]), "+f"(c[2]), "+f"(c[3])
        : "r"(a[0]), "r"(a[1]), "r"(a[2]), "r"(a[3]), "r"(b[0]), "r"(b[1]));
}
__device__ __forceinline__ void ldsm_x4(uint32_t* r, uint32_t addr) {
    asm volatile("ldmatrix.sync.aligned.m8n8.x4.shared.b16 {%0,%1,%2,%3}, [%4];"
                 : "=r"(r[0]), "=r"(r[1]), "=r"(r[2]), "=r"(r[3]) : "r"(addr));
}

// ---------------------------------------------------------------------------
// fp32 -> fp16 (rne) conversion pre-pass (memory-bound)
// ---------------------------------------------------------------------------
__global__ __launch_bounds__(256)
void f2h_kernel(const float* __restrict__ in, __half* __restrict__ out, int n4) {
    int i = blockIdx.x * blockDim.x + threadIdx.x;
    if (i < n4) {
        float4 v = ((const float4*)in)[i];
        __half2 h0 = __floats2half2_rn(v.x, v.y);
        __half2 h1 = __floats2half2_rn(v.z, v.w);
        ((__half2*)out)[2 * i]     = h0;
        ((__half2*)out)[2 * i + 1] = h1;
    }
}

// ---------------------------------------------------------------------------
// GEMM (mma.sync fp16 m16n8k16 + ldmatrix): out[m,o] = dot(U[m,:],W[o,:]) + epi
//   mode 0: float out, softplus(val + bias + bias2)
//   mode 1: half  out, val + bias
// 256 threads (8 warps), CTA tile 128x128, BK=64, cp.async double buffer.
// Warp grid 4(m) x 2(n): each warp 32x64 = 2 mtiles x 8 ntiles of m16n8k16.
// smem rows of 72 halves (144B) -> ldmatrix conflict-free phases.
// ---------------------------------------------------------------------------
#define HSTRIDE 72               // halves per row (64 + 8 pad)
#define TILE_B (128 * HSTRIDE * 2)       // bytes per tile = 18432
#define GEMM_SMEM (2 * 2 * TILE_B)       // 73728 bytes

__global__ __launch_bounds__(256, 2)
void gemm_mma_h(const __half* __restrict__ U, const __half* __restrict__ W,
                const float* __restrict__ bias, const float* __restrict__ bias2,
                void* __restrict__ outp, int Nout, int mode)
{
    extern __shared__ char smc[];
    const int tid = threadIdx.x;
    const int wid = tid >> 5;
    const int lane = tid & 31;
    const int bx = blockIdx.x;      // N tile
    const int by = blockIdx.y;      // M tile
    const int warp_m = wid & 3, warp_n = wid >> 2;
    const int m0 = warp_m * 32, n0 = warp_n * 64;
    const int g = lane >> 2, t4 = lane & 3;

    const __half* Ag = U + (size_t)(by * 128) * K_DIM;
    const __half* Bg = W + (size_t)(bx * 128) * K_DIM;

    // per-lane ldmatrix byte offsets within a tile
    const int sel = lane >> 3;      // x4 sub-matrix this lane addresses
    const int lr  = lane & 7;
    // A x4: {(m0..7,k0), (m8..15,k0), (m0..7,k8), (m8..15,k8)}
    uint32_t aoff[2];
#pragma unroll
    for (int mt = 0; mt < 2; ++mt) {
        int row = m0 + mt * 16 + lr + (sel & 1) * 8;
        int kh  = (sel >> 1) * 8;
        aoff[mt] = (uint32_t)((row * HSTRIDE + kh) * 2);
    }
    // B x4 (ntile pair): {(nt,k0), (nt,k8), (nt+1,k0), (nt+1,k8)}
    uint32_t boff[4];
#pragma unroll
    for (int ntp = 0; ntp < 4; ++ntp) {
        int row = n0 + (2 * ntp + (sel >> 1)) * 8 + lr;
        int kh  = (sel & 1) * 8;
        boff[ntp] = (uint32_t)((row * HSTRIDE + kh) * 2);
    }

    float acc[2][8][4];
#pragma unroll
    for (int mt = 0; mt < 2; ++mt)
#pragma unroll
        for (int nt = 0; nt < 8; ++nt)
#pragma unroll
            for (int j = 0; j < 4; ++j) acc[mt][nt][j] = 0.0f;

    const int NK = K_DIM / 64;      // 16 k-tiles
    const uint32_t sm_u = smem_u32(smc);

    auto issue = [&](int it, int buf) {
        char* As = smc + buf * 2 * TILE_B;
        char* Bs = As + TILE_B;
        const int kc = it * 64;
#pragma unroll
        for (int i = 0; i < 4; ++i) {
            int id = tid + i * 256;     // 0..1023 16B chunks per matrix
            int row = id >> 3;
            int q = id & 7;
            cp_async16(smem_u32(As + (row * HSTRIDE + q * 8) * 2),
                       Ag + (size_t)row * K_DIM + kc + q * 8);
            cp_async16(smem_u32(Bs + (row * HSTRIDE + q * 8) * 2),
                       Bg + (size_t)row * K_DIM + kc + q * 8);
        }
        asm volatile("cp.async.commit_group;" ::: "memory");
    };

    issue(0, 0);
    for (int it = 0; it < NK; ++it) {
        const int buf = it & 1;
        if (it + 1 < NK) {
            issue(it + 1, buf ^ 1);
            asm volatile("cp.async.wait_group 1;" ::: "memory");
        } else {
            asm volatile("cp.async.wait_group 0;" ::: "memory");
        }
        __syncthreads();

        const uint32_t As_u = sm_u + (uint32_t)(buf * 2 * TILE_B);
        const uint32_t Bs_u = As_u + (uint32_t)TILE_B;
#pragma unroll
        for (int ks = 0; ks < 4; ++ks) {
            const uint32_t kb = ks * 32;     // 16 halves per k-step
            uint32_t a[2][4], b[4][4];
            ldsm_x4(a[0], As_u + aoff[0] + kb);
            ldsm_x4(a[1], As_u + aoff[1] + kb);
#pragma unroll
            for (int ntp = 0; ntp < 4; ++ntp)
                ldsm_x4(b[ntp], Bs_u + boff[ntp] + kb);
#pragma unroll
            for (int mt = 0; mt < 2; ++mt)
#pragma unroll
                for (int nt = 0; nt < 8; ++nt)
                    mma_f16(acc[mt][nt], a[mt], &b[nt >> 1][(nt & 1) * 2]);
        }
        __syncthreads();
    }

    // Epilogue
#pragma unroll
    for (int nt = 0; nt < 8; ++nt) {
        const int col = bx * 128 + n0 + nt * 8 + t4 * 2;
        float b0 = bias[col], b1 = bias[col + 1];
        if (mode == 0) {
            float* out = (float*)outp;
            float e0 = bias2[col], e1 = bias2[col + 1];
#pragma unroll
            for (int mt = 0; mt < 2; ++mt) {
                const int row = by * 128 + m0 + mt * 16 + g;
                float v0 = softplus_f(acc[mt][nt][0] + b0 + e0);
                float v1 = softplus_f(acc[mt][nt][1] + b1 + e1);
                float v2 = softplus_f(acc[mt][nt][2] + b0 + e0);
                float v3 = softplus_f(acc[mt][nt][3] + b1 + e1);
                *(float2*)&out[(size_t)row * Nout + col] = make_float2(v0, v1);
                *(float2*)&out[(size_t)(row + 8) * Nout + col] = make_float2(v2, v3);
            }
        } else {
            __half* out = (__half*)outp;
#pragma unroll
            for (int mt = 0; mt < 2; ++mt) {
                const int row = by * 128 + m0 + mt * 16 + g;
                __half2 p0 = __floats2half2_rn(acc[mt][nt][0] + b0,
                                               acc[mt][nt][1] + b1);
                __half2 p1 = __floats2half2_rn(acc[mt][nt][2] + b0,
                                               acc[mt][nt][3] + b1);
                *(__half2*)&out[(size_t)row * Nout + col] = p0;
                *(__half2*)&out[(size_t)(row + 8) * Nout + col] = p1;
            }
        }
    }
}

// ---------------------------------------------------------------------------
// Chunked scan. Bt/Ct are fp16 now; state math stays fp32.
// ---------------------------------------------------------------------------
__global__ __launch_bounds__(256)
void scan_pass1(const float* __restrict__ u, const float* __restrict__ log_A,
                const float* __restrict__ dt, const __half* __restrict__ Bt,
                float* __restrict__ P, float* __restrict__ H)
{
    const int tid = threadIdx.x;
    const int lane = tid & 31;
    const int half = lane >> 4;
    const int n = lane & 15;
    const int warp = tid >> 5;
    const int p = blockIdx.x * 16 + warp * 2 + half;
    const int c = blockIdx.y;
    const int b = p >> 10;
    const int d = p & 1023;

    const float A = -expf(log_A[d * N_SZ + n]);
    const float invA = 1.0f / A;

    size_t base = (size_t)b * L_SZ * D_SZ + (size_t)c * CL * D_SZ + d;
    const float* dtp = dt + base;
    const float* up  = u + base;
    const __half* bp = Bt + base * N_SZ + n;

    float h = 0.0f, aprod = 1.0f;
#pragma unroll 4
    for (int t = 0; t < CL; ++t) {
        float a = __expf(*dtp * A);
        float x = (a - 1.0f) * invA * __half2float(*bp) * (*up);
        h = fmaf(a, h, x);
        aprod *= a;
        dtp += D_SZ; up += D_SZ; bp += (size_t)D_SZ * N_SZ;
    }
    const int idx = (p * NC + c) * N_SZ + n;
    P[idx] = aprod;
    H[idx] = h;
}

__global__ __launch_bounds__(256)
void scan_chain(const float* __restrict__ P, const float* __restrict__ H,
                float* __restrict__ hs)
{
    const int id = blockIdx.x * blockDim.x + threadIdx.x;
    const int p = id >> 4;
    const int n = id & 15;
    float h = 0.0f;
#pragma unroll
    for (int c = 0; c < NC; ++c) {
        const int idx = (p * NC + c) * N_SZ + n;
        hs[idx] = h;
        h = fmaf(P[idx], h, H[idx]);
    }
}

__global__ __launch_bounds__(256)
void scan_pass2(const float* __restrict__ u, const float* __restrict__ log_A,
                const float* __restrict__ D_skip,
                const float* __restrict__ dt, const __half* __restrict__ Bt,
                const __half* __restrict__ Ct, const float* __restrict__ hs,
                float* __restrict__ out)
{
    const int tid = threadIdx.x;
    const int lane = tid & 31;
    const int half = lane >> 4;
    const int n = lane & 15;
    const int warp = tid >> 5;
    const int p = blockIdx.x * 16 + warp * 2 + half;
    const int c = blockIdx.y;
    const int b = p >> 10;
    const int d = p & 1023;

    const float A = -expf(log_A[d * N_SZ + n]);
    const float invA = 1.0f / A;
    const float Dsk = D_skip[d];

    size_t base = (size_t)b * L_SZ * D_SZ + (size_t)c * CL * D_SZ + d;
    const float* dtp = dt + base;
    const float* up  = u + base;
    float* op        = out + base;
    const __half* bp = Bt + base * N_SZ + n;
    const __half* cp = Ct + base * N_SZ + n;

    float h = hs[(p * NC + c) * N_SZ + n];
#pragma unroll 4
    for (int t = 0; t < CL; ++t) {
        float uv = *up;
        float a = __expf(*dtp * A);
        float x = (a - 1.0f) * invA * __half2float(*bp) * uv;
        h = fmaf(a, h, x);
        float prod = __half2float(*cp) * h;
        prod += __shfl_xor_sync(0xffffffffu, prod, 1);
        prod += __shfl_xor_sync(0xffffffffu, prod, 2);
        prod += __shfl_xor_sync(0xffffffffu, prod, 4);
        prod += __shfl_xor_sync(0xffffffffu, prod, 8);
        if (n == 0) *op = fmaf(Dsk, uv, prod);
        dtp += D_SZ; up += D_SZ; op += D_SZ;
        bp += (size_t)D_SZ * N_SZ; cp += (size_t)D_SZ * N_SZ;
    }
}

// ---------------------------------------------------------------------------
// Launch. Inputs: u, log_A, D_skip, dt_bias, W_dt, b_dt, W_B, b_B, W_C, b_C
// ---------------------------------------------------------------------------
extern "C" void kernel_launch(void* const* d_in, const int* in_sizes, int n_in,
                              void* d_out, int out_size)
{
    const float* u       = (const float*)d_in[0];
    const float* log_A   = (const float*)d_in[1];
    const float* D_skip  = (const float*)d_in[2];
    const float* dt_bias = (const float*)d_in[3];
    const float* W_dt    = (const float*)d_in[4];
    const float* b_dt    = (const float*)d_in[5];
    const float* W_B     = (const float*)d_in[6];
    const float* b_B     = (const float*)d_in[7];
    const float* W_C     = (const float*)d_in[8];
    const float* b_C     = (const float*)d_in[9];
    float* out = (float*)d_out;

    float *dt_buf, *P, *H, *hs;
    __half *B_buf, *C_buf, *Uh, *Wdth, *WBh, *WCh;
    cudaGetSymbolAddress((void**)&dt_buf, g_dt);
    cudaGetSymbolAddress((void**)&B_buf, g_Bt);
    cudaGetSymbolAddress((void**)&C_buf, g_Ct);
    cudaGetSymbolAddress((void**)&Uh, g_Uh);
    cudaGetSymbolAddress((void**)&Wdth, g_Wdth);
    cudaGetSymbolAddress((void**)&WBh, g_WBh);
    cudaGetSymbolAddress((void**)&WCh, g_WCh);
    cudaGetSymbolAddress((void**)&P, g_P);
    cudaGetSymbolAddress((void**)&H, g_H);
    cudaGetSymbolAddress((void**)&hs, g_hs);

    cudaFuncSetAttribute(gemm_mma_h, cudaFuncAttributeMaxDynamicSharedMemorySize,
                         GEMM_SMEM);

    // fp16 conversion pre-pass (memory-bound)
    f2h_kernel<<<(M_TOT * K_DIM / 4 + 255) / 256, 256>>>(u, Uh, M_TOT * K_DIM / 4);
    f2h_kernel<<<(D_SZ * K_DIM / 4 + 255) / 256, 256>>>(W_dt, Wdth,
                                                        D_SZ * K_DIM / 4);
    f2h_kernel<<<(int)((size_t)NOUT_BC * K_DIM / 4 + 255) / 256, 256>>>(
        W_B, WBh, (int)((size_t)NOUT_BC * K_DIM / 4));
    f2h_kernel<<<(int)((size_t)NOUT_BC * K_DIM / 4 + 255) / 256, 256>>>(
        W_C, WCh, (int)((size_t)NOUT_BC * K_DIM / 4));

    // dt = softplus(u @ W_dt^T + b_dt + dt_bias)   (fp32 out)
    gemm_mma_h<<<dim3(D_SZ / 128, M_TOT / 128), 256, GEMM_SMEM>>>(
        Uh, Wdth, b_dt, dt_bias, dt_buf, D_SZ, 0);
    // Bt / Ct = u @ W^T + b   (fp16 out)
    gemm_mma_h<<<dim3(NOUT_BC / 128, M_TOT / 128), 256, GEMM_SMEM>>>(
        Uh, WBh, b_B, nullptr, B_buf, NOUT_BC, 1);
    gemm_mma_h<<<dim3(NOUT_BC / 128, M_TOT / 128), 256, GEMM_SMEM>>>(
        Uh, WCh, b_C, nullptr, C_buf, NOUT_BC, 1);

    // chunked scan
    dim3 sgrid(B_SZ * D_SZ / 16, NC);
    scan_pass1<<<sgrid, 256>>>(u, log_A, dt_buf, B_buf, P, H);
    scan_chain<<<B_SZ * D_SZ * N_SZ / 256, 256>>>(P, H, hs);
    scan_pass2<<<sgrid, 256>>>(u, log_A, D_skip, dt_buf, B_buf, C_buf, hs, out);
}